// round 11
// baseline (speedup 1.0000x reference)
#include <cuda_runtime.h>
#include <cuda_bf16.h>

#define X_DIM 4096
#define Z_DIM 64
#define N_HID 1024
#define ROW_LEN (X_DIM + 1)            // 4097 floats per W1 row
#define NROWS (Z_DIM * N_HID)          // 65536 total rows
#define THREADS 256
#define NWARPS (THREADS / 32)          // 8
#define NSM 148
#define CTAS_PER_SM 3
#define NBLOCKS (NSM * CTAS_PER_SM)    // 444 — exactly one resident wave
#define NGWARPS (NBLOCKS * NWARPS)     // 3552 resident warps

// 16B vector load, non-coherent, 256B L2 fetch granularity. Streams are
// contiguous per warp, so granules are fully consumed.
__device__ __forceinline__ float4 ldg_256B(const float4* p) {
    float4 w;
    asm volatile("ld.global.nc.L2::256B.v4.f32 {%0,%1,%2,%3}, [%4];"
                 : "=f"(w.x), "=f"(w.y), "=f"(w.z), "=f"(w.w)
                 : "l"(p));
    return w;
}

// Seed output with b2 (d_out is poisoned; main kernel accumulates into it).
__global__ void mlp_init_kernel(const float* __restrict__ b2, float* __restrict__ out) {
    int i = threadIdx.x;
    if (i < Z_DIM) out[i] = b2[i];
}

__global__ __launch_bounds__(THREADS, CTAS_PER_SM)
void mlp_main_kernel(const float* __restrict__ x,
                     const float* __restrict__ z,
                     const float* __restrict__ W1,
                     const float* __restrict__ b1,
                     const float* __restrict__ W2,
                     float* __restrict__ out) {
    __shared__ float xs[X_DIM];

    const int tid  = threadIdx.x;
    const int wid  = tid >> 5;
    const int lane = tid & 31;

    // Stage x into shared memory once per block (vectorized, coalesced).
    {
        const float4* x4 = reinterpret_cast<const float4*>(x);
        float4* xs4 = reinterpret_cast<float4*>(xs);
        #pragma unroll
        for (int i = tid; i < X_DIM / 4; i += THREADS) {
            xs4[i] = x4[i];
        }
    }
    __syncthreads();

    // Balanced contiguous row partition: warp gw owns rows [start, end).
    // 65536 / 3552 => 18 or 19 consecutive rows per warp => ONE contiguous
    // ~300 KB read stream per warp (3552 streams chip-wide, DRAM-row friendly).
    const int gw    = blockIdx.x * NWARPS + wid;
    const int start = (int)(((long long)gw * NROWS) / NGWARPS);
    const int end   = (int)(((long long)(gw + 1) * NROWS) / NGWARPS);
    const int nrows = end - start;                  // 18 or 19

    // Preload per-row epilogue params into lanes: lane l holds row start+l.
    // b1/W2 flattened over [Z_DIM*N_HID] have flat index == row.
    float b1v = 0.0f, w2v = 0.0f, zv = 0.0f;
    if (lane < nrows) {
        b1v = __ldg(&b1[start + lane]);
        w2v = __ldg(&W2[start + lane]);
        zv  = __ldg(&z[(start + lane) >> 10]);
    }

    int   cur_k = start >> 10;
    float facc  = 0.0f;                             // lane 0 only

    for (int r = 0; r < nrows; r++) {
        const int    row     = start + r;
        const size_t rowbase = (size_t)row * ROW_LEN;
        const int    p       = (4 - (row & 3)) & 3; // peel to 16B alignment
        const float* wrow    = W1 + rowbase;

        // Broadcast this row's epilogue params in UNIFORM control flow
        // (shuffles must not sit inside divergent branches).
        const float zk = __shfl_sync(0xFFFFFFFFu, zv,  r);
        const float bv = __shfl_sync(0xFFFFFFFFu, b1v, r);
        const float wv = __shfl_sync(0xFFFFFFFFu, w2v, r);

        float s = 0.0f;

        // Head peel: elements [0, p), lanes < p.
        if (lane < p) {
            s = __ldg(wrow + lane) * xs[lane];
        }

        // Bulk: contiguous aligned float4s over elements [p, p + 4*nv4).
        // Unroll 8 => 8 independent LDG.128 front-batched per iteration,
        // covering a contiguous 4 KB window per warp.
        const int nv4 = (X_DIM - p) >> 2;           // 1023 or 1024
        const float4* w4 = reinterpret_cast<const float4*>(wrow + p);
        #pragma unroll 8
        for (int c = lane; c < nv4; c += 32) {
            const float4 w = ldg_256B(w4 + c);
            const int e = p + 4 * c;
            s = fmaf(w.x, xs[e + 0], s);
            s = fmaf(w.y, xs[e + 1], s);
            s = fmaf(w.z, xs[e + 2], s);
            s = fmaf(w.w, xs[e + 3], s);
        }

        // Tail: elements [p + 4*nv4, 4097) — 1..4 elements including the
        // z-coefficient at element 4096.
        const int tstart = p + 4 * nv4;
        const int e = tstart + lane;
        if (e <= X_DIM) {
            const float mul = (e < X_DIM) ? xs[e] : zk;
            s = fmaf(__ldg(wrow + e), mul, s);
        }

        // Warp reduce row dot-product (uniform).
        #pragma unroll
        for (int o = 16; o > 0; o >>= 1)
            s += __shfl_xor_sync(0xFFFFFFFFu, s, o);

        // Flush accumulated contribution on head boundary (uniform branch —
        // row/cur_k are identical across the warp).
        const int k_r = row >> 10;
        if (k_r != cur_k) {
            if (lane == 0) atomicAdd(&out[cur_k], facc);
            facc  = 0.0f;
            cur_k = k_r;
        }
        if (lane == 0) {
            facc = fmaf(fmaxf(s + bv, 0.0f), wv, facc);
        }
    }

    if (lane == 0) atomicAdd(&out[cur_k], facc);
}

extern "C" void kernel_launch(void* const* d_in, const int* in_sizes, int n_in,
                              void* d_out, int out_size) {
    const float* x  = (const float*)d_in[0];
    const float* z  = (const float*)d_in[1];
    const float* W1 = (const float*)d_in[2];
    const float* b1 = (const float*)d_in[3];
    const float* W2 = (const float*)d_in[4];
    const float* b2 = (const float*)d_in[5];
    float* out = (float*)d_out;

    mlp_init_kernel<<<1, 64>>>(b2, out);
    mlp_main_kernel<<<NBLOCKS, THREADS>>>(x, z, W1, b1, W2, out);
}

// round 12
// speedup vs baseline: 1.0439x; 1.0439x over previous
#include <cuda_runtime.h>
#include <cuda_bf16.h>

#define X_DIM 4096
#define Z_DIM 64
#define N_HID 1024
#define ROW_LEN (X_DIM + 1)            // 4097 floats per W1 row
#define THREADS 256
#define NWARPS (THREADS / 32)          // 8
#define NSM 148
#define CTAS_PER_SM 3
#define NBLOCKS (NSM * CTAS_PER_SM)    // 444 — exactly one resident wave
#define ROWS_PER_TASK 8
#define NTASKS (Z_DIM * N_HID / ROWS_PER_TASK)   // 8192; task t -> rows 8t..8t+7
#define NV4_SHARED 1023                // bulk float4s per row (shared across phases)

// 16B vector load, non-coherent, 256B L2 fetch granularity.
__device__ __forceinline__ float4 ldg_256B(const float4* p) {
    float4 w;
    asm volatile("ld.global.nc.L2::256B.v4.f32 {%0,%1,%2,%3}, [%4];"
                 : "=f"(w.x), "=f"(w.y), "=f"(w.z), "=f"(w.w)
                 : "l"(p));
    return w;
}

// Seed output with b2 (d_out is poisoned; main kernel accumulates into it).
__global__ void mlp_init_kernel(const float* __restrict__ b2, float* __restrict__ out) {
    int i = threadIdx.x;
    if (i < Z_DIM) out[i] = b2[i];
}

__global__ __launch_bounds__(THREADS, CTAS_PER_SM)
void mlp_main_kernel(const float* __restrict__ x,
                     const float* __restrict__ z,
                     const float* __restrict__ W1,
                     const float* __restrict__ b1,
                     const float* __restrict__ W2,
                     float* __restrict__ out) {
    __shared__ float xs[X_DIM];

    const int tid  = threadIdx.x;
    const int wid  = tid >> 5;
    const int lane = tid & 31;
    const int b    = blockIdx.x;

    // Stage x into shared memory once per block (vectorized, coalesced).
    {
        const float4* x4 = reinterpret_cast<const float4*>(x);
        float4* xsv = reinterpret_cast<float4*>(xs);
        #pragma unroll
        for (int i = tid; i < X_DIM / 4; i += THREADS) {
            xsv[i] = x4[i];
        }
    }
    __syncthreads();

    const float4* xs4 = reinterpret_cast<const float4*>(xs);

    // Block-granular task striding (R8 scheme): block b owns tasks
    // {b + i*NBLOCKS}, round-robined over its 8 warps. Task t covers the
    // CONSECUTIVE rows 8t..8t+7 — one contiguous 128 KB window per task.
    // Row 8t starts at element 8t*4097 ≡ 0 (mod 4), so per-row alignment
    // phases are the compile-time pattern p[r] = (4 - (r&3)) & 3.
    for (int i = wid; ; i += NWARPS) {
        const int t = b + i * NBLOCKS;
        if (t >= NTASKS) break;

        const int j0 = t * ROWS_PER_TASK;       // first row of this task
        const int k  = j0 >> 10;                // head index (rows 8t..8t+7 share it)
        const float* wbase = W1 + (size_t)j0 * ROW_LEN;
        const float  zk    = __ldg(&z[k]);

        // Per-row aligned float4 base pointers (phase folded in).
        const float4* rp4[ROWS_PER_TASK];
        #pragma unroll
        for (int r = 0; r < ROWS_PER_TASK; r++) {
            const int p = (4 - (r & 3)) & 3;
            rp4[r] = reinterpret_cast<const float4*>(wbase + (size_t)r * ROW_LEN + p);
        }

        float s[ROWS_PER_TASK];
        #pragma unroll
        for (int r = 0; r < ROWS_PER_TASK; r++) s[r] = 0.0f;

        // Bulk: each row contributes a 16B-aligned LDG.128 stream over its
        // elements [p_r, p_r + 4092). xs window [4c, 4c+7] loaded as two
        // LDS.128; per-row phase selection is compile-time register picks.
        #pragma unroll 1
        for (int c = lane; c < NV4_SHARED; c += 32) {
            const float4 xa = xs4[c];
            const float4 xb = xs4[c + 1];
            const float v[8] = {xa.x, xa.y, xa.z, xa.w, xb.x, xb.y, xb.z, xb.w};
            #pragma unroll
            for (int r = 0; r < ROWS_PER_TASK; r++) {
                const int p = (4 - (r & 3)) & 3;
                const float4 w = ldg_256B(rp4[r] + c);
                s[r] = fmaf(w.x, v[p + 0], s[r]);
                s[r] = fmaf(w.y, v[p + 1], s[r]);
                s[r] = fmaf(w.z, v[p + 2], s[r]);
                s[r] = fmaf(w.w, v[p + 3], s[r]);
            }
        }

        // Head + tail peel: per row, the 5 uncovered elements are
        // {0..p_r-1} ∪ {p_r+4092..4096}; element 4096 multiplies z_k.
        if (lane < 5) {
            #pragma unroll
            for (int r = 0; r < ROWS_PER_TASK; r++) {
                const int p = (4 - (r & 3)) & 3;
                const int e = (lane < p) ? lane : (4092 + lane);
                const float mul = (e < X_DIM) ? xs[e] : zk;
                s[r] = fmaf(__ldg(wbase + (size_t)r * ROW_LEN + e), mul, s[r]);
            }
        }

        // Warp-reduce each row, fold relu(h) * W2 on lane 0, one atomic/task.
        float facc = 0.0f;
        #pragma unroll
        for (int r = 0; r < ROWS_PER_TASK; r++) {
            float v = s[r];
            #pragma unroll
            for (int o = 16; o > 0; o >>= 1)
                v += __shfl_xor_sync(0xFFFFFFFFu, v, o);
            if (lane == 0) {
                const int j = j0 + r;
                float h = v + __ldg(&b1[j]);
                facc = fmaf(fmaxf(h, 0.0f), __ldg(&W2[j]), facc);
            }
        }
        if (lane == 0) atomicAdd(&out[k], facc);
    }
}

extern "C" void kernel_launch(void* const* d_in, const int* in_sizes, int n_in,
                              void* d_out, int out_size) {
    const float* x  = (const float*)d_in[0];
    const float* z  = (const float*)d_in[1];
    const float* W1 = (const float*)d_in[2];
    const float* b1 = (const float*)d_in[3];
    const float* W2 = (const float*)d_in[4];
    const float* b2 = (const float*)d_in[5];
    float* out = (float*)d_out;

    mlp_init_kernel<<<1, 64>>>(b2, out);
    mlp_main_kernel<<<NBLOCKS, THREADS>>>(x, z, W1, b1, W2, out);
}

// round 13
// speedup vs baseline: 1.0613x; 1.0167x over previous
#include <cuda_runtime.h>
#include <cuda_bf16.h>

#define X_DIM 4096
#define Z_DIM 64
#define N_HID 1024
#define ROW_LEN (X_DIM + 1)            // 4097 floats per W1 row
#define THREADS 256
#define NWARPS (THREADS / 32)          // 8
#define NSM 148
#define CTAS_PER_SM 4
#define NBLOCKS (NSM * CTAS_PER_SM)    // 592 — exactly one resident wave
#define ROWS_PER_TASK 8
#define NTASKS (Z_DIM * N_HID / ROWS_PER_TASK)   // 8192; task t -> rows 8t..8t+7
#define NV4_SHARED 1023                // bulk float4s per row (shared across phases)

// 16B vector load, non-coherent, 256B L2 fetch granularity.
__device__ __forceinline__ float4 ldg_256B(const float4* p) {
    float4 w;
    asm volatile("ld.global.nc.L2::256B.v4.f32 {%0,%1,%2,%3}, [%4];"
                 : "=f"(w.x), "=f"(w.y), "=f"(w.z), "=f"(w.w)
                 : "l"(p));
    return w;
}

// Seed output with b2 (d_out is poisoned; main kernel accumulates into it).
__global__ void mlp_init_kernel(const float* __restrict__ b2, float* __restrict__ out) {
    int i = threadIdx.x;
    if (i < Z_DIM) out[i] = b2[i];
}

__global__ __launch_bounds__(THREADS, CTAS_PER_SM)
void mlp_main_kernel(const float* __restrict__ x,
                     const float* __restrict__ z,
                     const float* __restrict__ W1,
                     const float* __restrict__ b1,
                     const float* __restrict__ W2,
                     float* __restrict__ out) {
    __shared__ float xs[X_DIM];

    const int tid  = threadIdx.x;
    const int wid  = tid >> 5;
    const int lane = tid & 31;
    const int b    = blockIdx.x;

    // Stage x into shared memory once per block (vectorized, coalesced).
    {
        const float4* x4 = reinterpret_cast<const float4*>(x);
        float4* xsv = reinterpret_cast<float4*>(xs);
        #pragma unroll
        for (int i = tid; i < X_DIM / 4; i += THREADS) {
            xsv[i] = x4[i];
        }
    }
    __syncthreads();

    const float4* xs4 = reinterpret_cast<const float4*>(xs);

    // Block-granular task striding: block b owns tasks {b + i*NBLOCKS},
    // round-robined over its 8 warps. Task t covers CONSECUTIVE rows
    // 8t..8t+7 (one contiguous 128 KB window). Row 8t starts at element
    // 8t*4097 ≡ 0 (mod 4), so per-row alignment phases are the compile-time
    // pattern p[r] = (4 - (r&3)) & 3.
    for (int i = wid; ; i += NWARPS) {
        const int t = b + i * NBLOCKS;
        if (t >= NTASKS) break;

        const int j0 = t * ROWS_PER_TASK;       // first row of this task
        const int k  = j0 >> 10;                // head index (rows 8t..8t+7 share it)
        const float* wbase = W1 + (size_t)j0 * ROW_LEN;
        const float  zk    = __ldg(&z[k]);

        float s[ROWS_PER_TASK];
        #pragma unroll
        for (int r = 0; r < ROWS_PER_TASK; r++) s[r] = 0.0f;

        // Bulk: one advancing 16B-aligned base; each row's load address is
        // base + compile-time byte immediate ((r*4097 + p_r)*4), keeping
        // register pressure low (single address register pair). xs window
        // [4c, 4c+7] loaded as two LDS.128; per-row phase picks are static.
        #pragma unroll 1
        for (int c = lane; c < NV4_SHARED; c += 32) {
            const float4 xa = xs4[c];
            const float4 xb = xs4[c + 1];
            const float v[8] = {xa.x, xa.y, xa.z, xa.w, xb.x, xb.y, xb.z, xb.w};
            const char* cbase = reinterpret_cast<const char*>(wbase) + (size_t)c * 16;
            #pragma unroll
            for (int r = 0; r < ROWS_PER_TASK; r++) {
                const int p = (4 - (r & 3)) & 3;
                const float4 w = ldg_256B(
                    reinterpret_cast<const float4*>(cbase + (size_t)(r * ROW_LEN + p) * 4));
                s[r] = fmaf(w.x, v[p + 0], s[r]);
                s[r] = fmaf(w.y, v[p + 1], s[r]);
                s[r] = fmaf(w.z, v[p + 2], s[r]);
                s[r] = fmaf(w.w, v[p + 3], s[r]);
            }
        }

        // Head + tail peel: per row, the 5 uncovered elements are
        // {0..p_r-1} ∪ {p_r+4092..4096}; element 4096 multiplies z_k.
        if (lane < 5) {
            #pragma unroll
            for (int r = 0; r < ROWS_PER_TASK; r++) {
                const int p = (4 - (r & 3)) & 3;
                const int e = (lane < p) ? lane : (4092 + lane);
                const float mul = (e < X_DIM) ? xs[e] : zk;
                s[r] = fmaf(__ldg(wbase + (size_t)r * ROW_LEN + e), mul, s[r]);
            }
        }

        // Warp-reduce each row, fold relu(h) * W2 on lane 0, one atomic/task.
        float facc = 0.0f;
        #pragma unroll
        for (int r = 0; r < ROWS_PER_TASK; r++) {
            float v = s[r];
            #pragma unroll
            for (int o = 16; o > 0; o >>= 1)
                v += __shfl_xor_sync(0xFFFFFFFFu, v, o);
            if (lane == 0) {
                const int j = j0 + r;
                float h = v + __ldg(&b1[j]);
                facc = fmaf(fmaxf(h, 0.0f), __ldg(&W2[j]), facc);
            }
        }
        if (lane == 0) atomicAdd(&out[k], facc);
    }
}

extern "C" void kernel_launch(void* const* d_in, const int* in_sizes, int n_in,
                              void* d_out, int out_size) {
    const float* x  = (const float*)d_in[0];
    const float* z  = (const float*)d_in[1];
    const float* W1 = (const float*)d_in[2];
    const float* b1 = (const float*)d_in[3];
    const float* W2 = (const float*)d_in[4];
    const float* b2 = (const float*)d_in[5];
    float* out = (float*)d_out;

    mlp_init_kernel<<<1, 64>>>(b2, out);
    mlp_main_kernel<<<NBLOCKS, THREADS>>>(x, z, W1, b1, W2, out);
}

// round 14
// speedup vs baseline: 1.0748x; 1.0127x over previous
#include <cuda_runtime.h>
#include <cuda_bf16.h>

#define X_DIM 4096
#define Z_DIM 64
#define N_HID 1024
#define ROW_LEN (X_DIM + 1)            // 4097 floats per W1 row
#define THREADS 256
#define NWARPS (THREADS / 32)          // 8
#define NSM 148
#define CTAS_PER_SM 4
#define NBLOCKS (NSM * CTAS_PER_SM)    // 592 — exactly one resident wave
#define ROWS_PER_TASK 8
#define NTASKS (Z_DIM * N_HID / ROWS_PER_TASK)   // 8192; task t -> rows 8t..8t+7
#define NV4_SHARED 1023                // bulk float4s per row (shared across phases)

// Dynamic work queue cursor. Reset to 0 by the init kernel on every call, so
// graph replays are deterministic in total work.
__device__ int g_next_task;

// 16B vector load, non-coherent, 256B L2 fetch granularity. NOT volatile:
// the compiler is free to hoist/pipeline these across iterations.
__device__ __forceinline__ float4 ldg_256B(const float4* p) {
    float4 w;
    asm("ld.global.nc.L2::256B.v4.f32 {%0,%1,%2,%3}, [%4];"
        : "=f"(w.x), "=f"(w.y), "=f"(w.z), "=f"(w.w)
        : "l"(p));
    return w;
}

// Seed output with b2 and reset the work queue (d_out is poisoned each run).
__global__ void mlp_init_kernel(const float* __restrict__ b2, float* __restrict__ out) {
    int i = threadIdx.x;
    if (i < Z_DIM) out[i] = b2[i];
    if (i == 0) g_next_task = 0;
}

__global__ __launch_bounds__(THREADS, CTAS_PER_SM)
void mlp_main_kernel(const float* __restrict__ x,
                     const float* __restrict__ z,
                     const float* __restrict__ W1,
                     const float* __restrict__ b1,
                     const float* __restrict__ W2,
                     float* __restrict__ out) {
    __shared__ float xs[X_DIM];

    const int tid  = threadIdx.x;
    const int lane = tid & 31;

    // Stage x into shared memory once per block (vectorized, coalesced).
    {
        const float4* x4 = reinterpret_cast<const float4*>(x);
        float4* xsv = reinterpret_cast<float4*>(xs);
        #pragma unroll
        for (int i = tid; i < X_DIM / 4; i += THREADS) {
            xsv[i] = x4[i];
        }
    }
    __syncthreads();

    const float4* xs4 = reinterpret_cast<const float4*>(xs);

    // Dynamic task claim: one global counter; lane 0 claims, warp follows.
    // Task t covers CONSECUTIVE rows 8t..8t+7 (a contiguous 128 KB window).
    // Row 8t starts at element 8t*4097 ≡ 0 (mod 4), so per-row alignment
    // phases are the compile-time pattern p[r] = (4 - (r&3)) & 3.
    for (;;) {
        int t;
        if (lane == 0) t = atomicAdd(&g_next_task, 1);
        t = __shfl_sync(0xFFFFFFFFu, t, 0);
        if (t >= NTASKS) break;

        const int j0 = t * ROWS_PER_TASK;       // first row of this task
        const int k  = j0 >> 10;                // head index (rows 8t..8t+7 share it)
        const float* wbase = W1 + (size_t)j0 * ROW_LEN;
        const float  zk    = __ldg(&z[k]);

        float s[ROWS_PER_TASK];
        #pragma unroll
        for (int r = 0; r < ROWS_PER_TASK; r++) s[r] = 0.0f;

        // Bulk: one advancing 16B-aligned base; each row's load address is
        // base + compile-time byte immediate ((r*4097 + p_r)*4). xs window
        // [4c, 4c+7] loaded as two LDS.128; per-row phase picks are static.
        #pragma unroll 1
        for (int c = lane; c < NV4_SHARED; c += 32) {
            const float4 xa = xs4[c];
            const float4 xb = xs4[c + 1];
            const float v[8] = {xa.x, xa.y, xa.z, xa.w, xb.x, xb.y, xb.z, xb.w};
            const char* cbase = reinterpret_cast<const char*>(wbase) + (size_t)c * 16;
            #pragma unroll
            for (int r = 0; r < ROWS_PER_TASK; r++) {
                const int p = (4 - (r & 3)) & 3;
                const float4 w = ldg_256B(
                    reinterpret_cast<const float4*>(cbase + (size_t)(r * ROW_LEN + p) * 4));
                s[r] = fmaf(w.x, v[p + 0], s[r]);
                s[r] = fmaf(w.y, v[p + 1], s[r]);
                s[r] = fmaf(w.z, v[p + 2], s[r]);
                s[r] = fmaf(w.w, v[p + 3], s[r]);
            }
        }

        // Head + tail peel: per row, the 5 uncovered elements are
        // {0..p_r-1} ∪ {p_r+4092..4096}; element 4096 multiplies z_k.
        if (lane < 5) {
            #pragma unroll
            for (int r = 0; r < ROWS_PER_TASK; r++) {
                const int p = (4 - (r & 3)) & 3;
                const int e = (lane < p) ? lane : (4092 + lane);
                const float mul = (e < X_DIM) ? xs[e] : zk;
                s[r] = fmaf(__ldg(wbase + (size_t)r * ROW_LEN + e), mul, s[r]);
            }
        }

        // Warp-reduce each row, fold relu(h) * W2 on lane 0, one atomic/task.
        float facc = 0.0f;
        #pragma unroll
        for (int r = 0; r < ROWS_PER_TASK; r++) {
            float v = s[r];
            #pragma unroll
            for (int o = 16; o > 0; o >>= 1)
                v += __shfl_xor_sync(0xFFFFFFFFu, v, o);
            if (lane == 0) {
                const int j = j0 + r;
                float h = v + __ldg(&b1[j]);
                facc = fmaf(fmaxf(h, 0.0f), __ldg(&W2[j]), facc);
            }
        }
        if (lane == 0) atomicAdd(&out[k], facc);
    }
}

extern "C" void kernel_launch(void* const* d_in, const int* in_sizes, int n_in,
                              void* d_out, int out_size) {
    const float* x  = (const float*)d_in[0];
    const float* z  = (const float*)d_in[1];
    const float* W1 = (const float*)d_in[2];
    const float* b1 = (const float*)d_in[3];
    const float* W2 = (const float*)d_in[4];
    const float* b2 = (const float*)d_in[5];
    float* out = (float*)d_out;

    mlp_init_kernel<<<1, 64>>>(b2, out);
    mlp_main_kernel<<<NBLOCKS, THREADS>>>(x, z, W1, b1, W2, out);
}